// round 10
// baseline (speedup 1.0000x reference)
#include <cuda_runtime.h>
#include <cuda_bf16.h>
#include <cstdint>

#define BB 2
#define SS 2048
#define HH 16
#define WW 31
#define K2 3072            // interleave-3: 1024 fp32 -> 3072 bf16
#define NSTAGE 3
#define AROWB 144          // padded smem row bytes (64 bf16 + 16 pad)
#define ASZ (128 * AROWB)  // 18432
#define BSZ (256 * AROWB)  // 36864
#define STAGE (ASZ + BSZ)  // 55296
#define SMEMSZ (NSTAGE * STAGE)   // 165888

// ---------------- device scratch -------------------------------------------
__device__ __align__(16) __nv_bfloat16 g_afsq[2048u * K2];
__device__ __align__(16) __nv_bfloat16 g_apx [6144u * K2];   // [pos(2048); x(4096)]
__device__ __align__(16) __nv_bfloat16 g_aatt[4096u * K2];
__device__ __align__(16) __nv_bfloat16 g_bqkv[3072u * K2];
__device__ __align__(16) __nv_bfloat16 g_bo  [1024u * K2];
__device__ float g_C1 [2048u * 3072];   // [qh | fsqk | fsqv]
__device__ float g_C23[6144u * 2048];   // rows 0-2047: [posk|posv]; 2048+: [xk|xv]
__device__ float g_bias3[3072];

// ---------------- helpers ---------------------------------------------------
__device__ __forceinline__ uint32_t smem_to_u32(const void* p) {
    uint32_t a;
    asm("{ .reg .u64 t; cvta.to.shared.u64 t, %1; cvt.u32.u64 %0, t; }"
        : "=r"(a) : "l"(p));
    return a;
}
__device__ __forceinline__ void cp16(uint32_t s, const void* g) {
    asm volatile("cp.async.cg.shared.global [%0], [%1], 16;" :: "r"(s), "l"(g));
}
__device__ __forceinline__ void ldsm4(uint32_t* r, uint32_t addr) {
    asm volatile("ldmatrix.sync.aligned.m8n8.x4.shared.b16 {%0,%1,%2,%3}, [%4];"
                 : "=r"(r[0]), "=r"(r[1]), "=r"(r[2]), "=r"(r[3]) : "r"(addr));
}
__device__ __forceinline__ void mma16816(float* c, const uint32_t* a, const uint32_t* b) {
    asm volatile(
        "mma.sync.aligned.m16n8k16.row.col.f32.bf16.bf16.f32 "
        "{%0,%1,%2,%3}, {%4,%5,%6,%7}, {%8,%9}, {%0,%1,%2,%3};"
        : "+f"(c[0]), "+f"(c[1]), "+f"(c[2]), "+f"(c[3])
        : "r"(a[0]), "r"(a[1]), "r"(a[2]), "r"(a[3]), "r"(b[0]), "r"(b[1]));
}
__device__ __forceinline__ void split2(float a, unsigned short& h, unsigned short& l) {
    __nv_bfloat16 hb = __float2bfloat16_rn(a);
    __nv_bfloat16 lb = __float2bfloat16_rn(a - __bfloat162float(hb));
    h = __bfloat16_as_ushort(hb);
    l = __bfloat16_as_ushort(lb);
}

// pack 8 fp32 -> 24 bf16 triples.  a_side: (h,l,h);  b_side: (h,h,l)
template <bool ASIDE>
__device__ __forceinline__ void pack_triples(const float* f, __nv_bfloat16* dst) {
    unsigned short t[24];
#pragma unroll
    for (int i = 0; i < 8; i++) {
        unsigned short h, l;
        split2(f[i], h, l);
        if (ASIDE) { t[3 * i] = h; t[3 * i + 1] = l; t[3 * i + 2] = h; }
        else       { t[3 * i] = h; t[3 * i + 1] = h; t[3 * i + 2] = l; }
    }
    uint32_t u[12];
#pragma unroll
    for (int j = 0; j < 12; j++)
        u[j] = (uint32_t)t[2 * j] | ((uint32_t)t[2 * j + 1] << 16);
    uint4* q = (uint4*)dst;
    q[0] = make_uint4(u[0], u[1], u[2], u[3]);
    q[1] = make_uint4(u[4], u[5], u[6], u[7]);
    q[2] = make_uint4(u[8], u[9], u[10], u[11]);
}

// ---------------- merged prep kernel ----------------------------------------
__global__ __launch_bounds__(256) void prep_all(
    const float* __restrict__ x, const float* __restrict__ fsq,
    const float* __restrict__ pos,
    const float* __restrict__ Wq, const float* __restrict__ Wk,
    const float* __restrict__ Wv, const float* __restrict__ Wo,
    const float* __restrict__ bq, const float* __restrict__ bk,
    const float* __restrict__ bv) {
    if (blockIdx.x < 2048) {
        int gi = blockIdx.x * 256 + threadIdx.x;   // 4096*128
        if (gi < 3072)
            g_bias3[gi] = gi < 1024 ? bq[gi] : (gi < 2048 ? bk[gi - 1024] : bv[gi - 2048]);
        int n = gi >> 7, kb = gi & 127;
        float f[8];
        if (n < 3072) {
            int sel = n >> 10, nn = n & 1023, h = nn >> 6, e = nn & 63;
            const float* W = sel == 0 ? Wq : (sel == 1 ? Wk : Wv);
            const float* src = W + ((size_t)h << 16) + (size_t)(kb * 8) * 64 + e;
#pragma unroll
            for (int i = 0; i < 8; i++) f[i] = src[i * 64];
            pack_triples<false>(f, g_bqkv + (size_t)n * K2 + kb * 24);
        } else {
            int n2 = n - 3072;
#pragma unroll
            for (int i = 0; i < 8; i++) f[i] = Wo[(size_t)(kb * 8 + i) * 1024 + n2];
            pack_triples<false>(f, g_bo + (size_t)n2 * K2 + kb * 24);
        }
    } else {
        int idx = (blockIdx.x - 2048) * 256 + threadIdx.x;   // 8192*128
        int r = idx >> 7, k8 = idx & 127;
        const float* src;
        __nv_bfloat16* dst;
        if (r < 2048)      { src = fsq + (size_t)r * 1024;          dst = g_afsq + (size_t)r * K2; }
        else if (r < 4096) { src = pos + (size_t)(r - 2048) * 1024; dst = g_apx + (size_t)(r - 2048) * K2; }
        else               { src = x   + (size_t)(r - 4096) * 1024; dst = g_apx + (size_t)(r - 2048) * K2; }
        const float4* p = (const float4*)(src + k8 * 8);
        float4 v0 = p[0], v1 = p[1];
        float f[8] = {v0.x, v0.y, v0.z, v0.w, v1.x, v1.y, v1.z, v1.w};
        pack_triples<true>(f, dst + k8 * 24);
    }
}

// ---------------- bf16 mma.sync GEMM body ------------------------------------
// C[m0:+128, n0:+256](+bias) = A[m0:+128,K2] @ B[n0:+256,K2]^T
// 8 warps (2x4), warp tile 64x64, BK=64, 3-stage cp.async,
// LDSM.x4 feed with register double-buffered fragments.
__device__ __forceinline__ void gemm_body(
    const __nv_bfloat16* __restrict__ A, const __nv_bfloat16* __restrict__ B,
    const float* __restrict__ bias, float* __restrict__ C,
    int Ntot, int m0, int n0, unsigned char* sm)
{
    const int tid = threadIdx.x;
    const int wid = tid >> 5, lane = tid & 31;
    const int wr = wid >> 2, wc = wid & 3;    // warp grid 2x4, warp tile 64x64

    const unsigned char* Ag = (const unsigned char*)A + (size_t)m0 * (K2 * 2);
    const unsigned char* Bg = (const unsigned char*)B + (size_t)n0 * (K2 * 2);

    const uint32_t smb = smem_to_u32(sm);
    const int lr = tid >> 1, lh = tid & 1;            // loader: row, 64B half
    const uint32_t adst = smb + lr * AROWB + lh * 64;
    const uint32_t bdst = adst + ASZ;
    const size_t goff = (size_t)lr * (K2 * 2) + lh * 64;

    // ldmatrix lane bases
    const uint32_t a_lm = smb + (uint32_t)(wr * 64 + (lane & 15)) * AROWB + (lane >> 4) * 16;
    const uint32_t b_lm = smb + ASZ
        + (uint32_t)(wc * 64 + (lane >> 4) * 8 + (lane & 7)) * AROWB
        + ((lane >> 3) & 1) * 16;

    auto load_stage = [&](int st, int c) {
        uint32_t d = st * STAGE;
        const unsigned char* ag = Ag + goff + (size_t)c * 128;
#pragma unroll
        for (int i = 0; i < 4; i++) cp16(adst + d + i * 16, ag + i * 16);
        const unsigned char* bg0 = Bg + goff + (size_t)c * 128;
        const unsigned char* bg1 = bg0 + (size_t)128 * (K2 * 2);
#pragma unroll
        for (int i = 0; i < 4; i++) cp16(bdst + d + i * 16, bg0 + i * 16);
#pragma unroll
        for (int i = 0; i < 4; i++) cp16(bdst + d + 128 * AROWB + i * 16, bg1 + i * 16);
        asm volatile("cp.async.commit_group;" ::: "memory");
    };

    float acc[4][8][4];
#pragma unroll
    for (int i = 0; i < 4; i++)
#pragma unroll
        for (int j = 0; j < 8; j++)
#pragma unroll
            for (int k = 0; k < 4; k++) acc[i][j][k] = 0.f;

    uint32_t afr[2][4][4], bfr[2][8][2];
    auto ldfr = [&](int buf, uint32_t soff, int ks) {
        const uint32_t ko = soff + ks * 32;
#pragma unroll
        for (int mi = 0; mi < 4; mi++)
            ldsm4(afr[buf][mi], a_lm + ko + (uint32_t)(mi * 16) * AROWB);
#pragma unroll
        for (int j = 0; j < 4; j++) {
            uint32_t r4[4];
            ldsm4(r4, b_lm + ko + (uint32_t)(j * 16) * AROWB);
            bfr[buf][2 * j][0] = r4[0]; bfr[buf][2 * j][1] = r4[1];
            bfr[buf][2 * j + 1][0] = r4[2]; bfr[buf][2 * j + 1][1] = r4[3];
        }
    };

    load_stage(0, 0);
    load_stage(1, 1);

    const int NCH = K2 / 64;   // 48
    int st = 0;
    for (int c = 0; c < NCH; c++) {
        if (c + 2 < NCH) asm volatile("cp.async.wait_group 1;" ::: "memory");
        else             asm volatile("cp.async.wait_group 0;" ::: "memory");
        __syncthreads();
        if (c + 2 < NCH) {
            int st2 = st + 2; if (st2 >= NSTAGE) st2 -= NSTAGE;
            load_stage(st2, c + 2);
        }

        const uint32_t soff = st * STAGE;
        ldfr(0, soff, 0);
#pragma unroll
        for (int ks = 0; ks < 4; ks++) {
            if (ks < 3) ldfr((ks + 1) & 1, soff, ks + 1);
            const int cur = ks & 1;
#pragma unroll
            for (int mi = 0; mi < 4; mi++)
#pragma unroll
                for (int ni = 0; ni < 8; ni++)
                    mma16816(acc[mi][ni], afr[cur][mi], bfr[cur][ni]);
        }
        if (++st == NSTAGE) st = 0;
    }

    // epilogue: bias + direct STG
    const int ccol = n0 + wc * 64 + (lane & 3) * 2;
    float bvv[8][2];
#pragma unroll
    for (int ni = 0; ni < 8; ni++) {
        bvv[ni][0] = bias[ccol + ni * 8];
        bvv[ni][1] = bias[ccol + ni * 8 + 1];
    }
    const int crow = m0 + wr * 64 + (lane >> 2);
#pragma unroll
    for (int mi = 0; mi < 4; mi++) {
#pragma unroll
        for (int hf = 0; hf < 2; hf++) {
            float* cp = C + (size_t)(crow + mi * 16 + hf * 8) * Ntot + ccol;
#pragma unroll
            for (int ni = 0; ni < 8; ni++) {
                float2 v = make_float2(acc[mi][ni][hf * 2] + bvv[ni][0],
                                       acc[mi][ni][hf * 2 + 1] + bvv[ni][1]);
                *(float2*)(cp + ni * 8) = v;
            }
        }
    }
}

// Merged projection GEMMs: blocks 0..191 -> C1 (2048x3072), 192..575 -> C23
__global__ __launch_bounds__(256) void gemm_merged() {
    extern __shared__ __align__(16) unsigned char sm[];
    int bid = blockIdx.x;
    if (bid < 192) {
        int mb = bid / 12, nb = bid % 12;
        gemm_body(g_afsq, g_bqkv, g_bias3, g_C1, 3072, mb * 128, nb * 256, sm);
    } else {
        int t = bid - 192;
        int mb = t / 8, nb = t % 8;
        gemm_body(g_apx, g_bqkv + (size_t)1024 * K2, g_bias3 + 1024, g_C23,
                  2048, mb * 128, nb * 256, sm);
    }
}

// Output GEMM: out[4096,1024] = aatt @ bo^T + bo_bias
__global__ __launch_bounds__(256) void gemm_out(const float* __restrict__ bias,
                                                float* __restrict__ C) {
    extern __shared__ __align__(16) unsigned char sm[];
    gemm_body(g_aatt, g_bo, bias, C, 1024, blockIdx.y * 128, blockIdx.x * 256, sm);
}

// ---------------- attention (smem scores, single-expf-per-key) --------------
__global__ __launch_bounds__(256) void attn_kernel(const float* __restrict__ bk,
                                                   const float* __restrict__ bv) {
    __shared__ float ssc[8][34];
    const int w = threadIdx.x >> 5;
    const int gw = (blockIdx.x * 256 + threadIdx.x) >> 5;
    const int lane = threadIdx.x & 31;
    const int s = gw & (SS - 1);
    const int h = (gw >> 11) & (HH - 1);
    const int b = gw >> 15;
    const int e = (h << 6) + 2 * lane;   // this thread covers elements e, e+1

    float* mysc = ssc[w];
    const float* xkv = g_C23 + (size_t)2048 * 2048;   // xk|xv rows

    const float2 q = *(const float2*)(g_C1 + (size_t)s * 3072 + e);

#pragma unroll
    for (int k = 0; k < WW; k++) {
        const int t = s + k - 15;
        float2 kv;
        if ((unsigned)t < SS) kv = *(const float2*)(xkv + (size_t)((b << 11) + t) * 2048 + e);
        else                  kv = *(const float2*)(bk + e);
        float p = q.x * kv.x + q.y * kv.y;
#pragma unroll
        for (int o = 16; o; o >>= 1) p += __shfl_xor_sync(0xffffffffu, p, o);
        if (lane == 0) mysc[k] = p * 0.125f;
    }
    {
        const float2 kv = *(const float2*)(g_C23 + (size_t)s * 2048 + e);
        float p = q.x * kv.x + q.y * kv.y;
#pragma unroll
        for (int o = 16; o; o >>= 1) p += __shfl_xor_sync(0xffffffffu, p, o);
        if (lane == 0) mysc[31] = p * 0.125f;
    }
    {
        const float2 kv = *(const float2*)(g_C1 + (size_t)s * 3072 + 1024 + e);
        float p = q.x * kv.x + q.y * kv.y;
#pragma unroll
        for (int o = 16; o; o >>= 1) p += __shfl_xor_sync(0xffffffffu, p, o);
        if (lane == 0) mysc[32] = p * 0.125f;
    }
    __syncwarp();

    float m = mysc[0];
#pragma unroll
    for (int k = 1; k < 33; k++) m = fmaxf(m, mysc[k]);

    float svk = mysc[lane];
    float ex = expf(svk - m);
    float ex32 = (lane == 0) ? expf(mysc[32] - m) : 0.f;
    __syncwarp();
    mysc[lane] = ex;
    if (lane == 0) mysc[32] = ex32;
    __syncwarp();

    float denom = 0.f;
#pragma unroll
    for (int k = 0; k < 33; k++) denom += mysc[k];
    const float inv = 1.f / denom;

    float o0 = 0.f, o1 = 0.f;
#pragma unroll
    for (int k = 0; k < WW; k++) {
        const int t = s + k - 15;
        float2 vv;
        if ((unsigned)t < SS) vv = *(const float2*)(xkv + (size_t)((b << 11) + t) * 2048 + 1024 + e);
        else                  vv = *(const float2*)(bv + e);
        const float wk = mysc[k];
        o0 += wk * vv.x; o1 += wk * vv.y;
    }
    {
        const float2 vv = *(const float2*)(g_C23 + (size_t)s * 2048 + 1024 + e);
        o0 += mysc[31] * vv.x; o1 += mysc[31] * vv.y;
    }
    {
        const float2 vv = *(const float2*)(g_C1 + (size_t)s * 3072 + 2048 + e);
        o0 += mysc[32] * vv.x; o1 += mysc[32] * vv.y;
    }

    unsigned short h0, l0, h1, l1;
    split2(o0 * inv, h0, l0);
    split2(o1 * inv, h1, l1);
    const int row = (b << 11) + s;
    uint32_t* p32 = (uint32_t*)(g_aatt + (size_t)row * K2 + 3 * e);
    p32[0] = (uint32_t)h0 | ((uint32_t)l0 << 16);
    p32[1] = (uint32_t)h0 | ((uint32_t)h1 << 16);
    p32[2] = (uint32_t)l1 | ((uint32_t)h1 << 16);
}

// ---------------- launch ----------------------------------------------------
extern "C" void kernel_launch(void* const* d_in, const int* in_sizes, int n_in,
                              void* d_out, int out_size) {
    const float* x   = (const float*)d_in[0];
    const float* fsq = (const float*)d_in[1];
    const float* pos = (const float*)d_in[2];
    const float* Wq  = (const float*)d_in[3];
    const float* bq  = (const float*)d_in[4];
    const float* Wk  = (const float*)d_in[5];
    const float* bk  = (const float*)d_in[6];
    const float* Wv  = (const float*)d_in[7];
    const float* bv  = (const float*)d_in[8];
    const float* Wo  = (const float*)d_in[9];
    const float* bo  = (const float*)d_in[10];
    float* out = (float*)d_out;

    cudaFuncSetAttribute(gemm_merged, cudaFuncAttributeMaxDynamicSharedMemorySize, SMEMSZ);
    cudaFuncSetAttribute(gemm_out,    cudaFuncAttributeMaxDynamicSharedMemorySize, SMEMSZ);

    prep_all<<<6144, 256>>>(x, fsq, pos, Wq, Wk, Wv, Wo, bq, bk, bv);
    gemm_merged<<<576, 256, SMEMSZ>>>();
    attn_kernel<<<8192, 256>>>(bk, bv);
    gemm_out<<<dim3(4, 32), 256, SMEMSZ>>>(bo, out);
}

// round 11
// speedup vs baseline: 1.4143x; 1.4143x over previous
#include <cuda_runtime.h>
#include <cuda_bf16.h>
#include <cuda_fp16.h>
#include <cstdint>

#define BB 2
#define SS 2048
#define HH 16
#define WW 31
#define K2 2048            // fp16 interleave-2: 1024 fp32 -> 2048 fp16
#define STAGES 4
#define AROWB 80           // padded smem row bytes (32 fp16 + 8 pad)
#define ASZ (128 * AROWB)  // A stage bytes
#define BSZ (256 * AROWB)  // B stage bytes
#define STAGE (ASZ + BSZ)  // 30720
#define SMEMSZ (STAGES * STAGE)

// ---------------- device scratch -------------------------------------------
__device__ __align__(16) __half g_afsq[2048u * K2];
__device__ __align__(16) __half g_apx [6144u * K2];   // [pos(2048); x(4096)]
__device__ __align__(16) __half g_aatt[4096u * K2];
__device__ __align__(16) __half g_bqkv[3072u * K2];
__device__ __align__(16) __half g_bo  [1024u * K2];
__device__ float g_C1 [2048u * 3072];   // [qh | fsqk | fsqv]
__device__ float g_C23[6144u * 2048];   // rows 0-2047: [posk|posv]; 2048+: [xk|xv]
__device__ float g_bias3[3072];

// ---------------- helpers ---------------------------------------------------
__device__ __forceinline__ uint32_t smem_to_u32(const void* p) {
    uint32_t a;
    asm("{ .reg .u64 t; cvta.to.shared.u64 t, %1; cvt.u32.u64 %0, t; }"
        : "=r"(a) : "l"(p));
    return a;
}
__device__ __forceinline__ void cp16(uint32_t s, const void* g) {
    asm volatile("cp.async.cg.shared.global [%0], [%1], 16;" :: "r"(s), "l"(g));
}
__device__ __forceinline__ void ldsm4(uint32_t* r, uint32_t addr) {
    asm volatile("ldmatrix.sync.aligned.m8n8.x4.shared.b16 {%0,%1,%2,%3}, [%4];"
                 : "=r"(r[0]), "=r"(r[1]), "=r"(r[2]), "=r"(r[3]) : "r"(addr));
}
__device__ __forceinline__ void mma16816(float* c, const uint32_t* a, const uint32_t* b) {
    asm volatile(
        "mma.sync.aligned.m16n8k16.row.col.f32.f16.f16.f32 "
        "{%0,%1,%2,%3}, {%4,%5,%6,%7}, {%8,%9}, {%0,%1,%2,%3};"
        : "+f"(c[0]), "+f"(c[1]), "+f"(c[2]), "+f"(c[3])
        : "r"(a[0]), "r"(a[1]), "r"(a[2]), "r"(a[3]), "r"(b[0]), "r"(b[1]));
}
// fp16 split: h = fp16(a), l = fp16(a - h)
__device__ __forceinline__ void split2f(float a, unsigned short& h, unsigned short& l) {
    __half hb = __float2half_rn(a);
    __half lb = __float2half_rn(a - __half2float(hb));
    h = __half_as_ushort(hb);
    l = __half_as_ushort(lb);
}

// pack 8 fp32 -> 16 fp16 pairs -> 2x uint4 stores.
// a_side: (h, l);  b_side: (h, h)
template <bool ASIDE>
__device__ __forceinline__ void pack_pairs(const float* f, __half* dst) {
    uint32_t u[8];
#pragma unroll
    for (int i = 0; i < 8; i++) {
        unsigned short h, l;
        split2f(f[i], h, l);
        u[i] = (uint32_t)h | ((uint32_t)(ASIDE ? l : h) << 16);
    }
    uint4* q = (uint4*)dst;
    q[0] = make_uint4(u[0], u[1], u[2], u[3]);
    q[1] = make_uint4(u[4], u[5], u[6], u[7]);
}

// ---------------- merged prep kernel ----------------------------------------
__global__ __launch_bounds__(256) void prep_all(
    const float* __restrict__ x, const float* __restrict__ fsq,
    const float* __restrict__ pos,
    const float* __restrict__ Wq, const float* __restrict__ Wk,
    const float* __restrict__ Wv, const float* __restrict__ Wo,
    const float* __restrict__ bq, const float* __restrict__ bk,
    const float* __restrict__ bv) {
    if (blockIdx.x < 2048) {
        int gi = blockIdx.x * 256 + threadIdx.x;   // 4096*128
        if (gi < 3072)
            g_bias3[gi] = gi < 1024 ? bq[gi] : (gi < 2048 ? bk[gi - 1024] : bv[gi - 2048]);
        int n = gi >> 7, kb = gi & 127;
        float f[8];
        if (n < 3072) {
            int sel = n >> 10, nn = n & 1023, h = nn >> 6, e = nn & 63;
            const float* W = sel == 0 ? Wq : (sel == 1 ? Wk : Wv);
            const float* src = W + ((size_t)h << 16) + (size_t)(kb * 8) * 64 + e;
#pragma unroll
            for (int i = 0; i < 8; i++) f[i] = src[i * 64];
            pack_pairs<false>(f, g_bqkv + (size_t)n * K2 + kb * 16);
        } else {
            int n2 = n - 3072;
#pragma unroll
            for (int i = 0; i < 8; i++) f[i] = Wo[(size_t)(kb * 8 + i) * 1024 + n2];
            pack_pairs<false>(f, g_bo + (size_t)n2 * K2 + kb * 16);
        }
    } else {
        int idx = (blockIdx.x - 2048) * 256 + threadIdx.x;   // 8192*128
        int r = idx >> 7, k8 = idx & 127;
        const float* src;
        __half* dst;
        if (r < 2048)      { src = fsq + (size_t)r * 1024;          dst = g_afsq + (size_t)r * K2; }
        else if (r < 4096) { src = pos + (size_t)(r - 2048) * 1024; dst = g_apx + (size_t)(r - 2048) * K2; }
        else               { src = x   + (size_t)(r - 4096) * 1024; dst = g_apx + (size_t)(r - 2048) * K2; }
        const float4* p = (const float4*)(src + k8 * 8);
        float4 v0 = p[0], v1 = p[1];
        float f[8] = {v0.x, v0.y, v0.z, v0.w, v1.x, v1.y, v1.z, v1.w};
        pack_pairs<true>(f, dst + k8 * 16);
    }
}

// ---------------- fp16 mma.sync GEMM body (ldmatrix feed) --------------------
// C[m0:+128, n0:+256](+bias) = A[m0:+128,K2] @ B[n0:+256,K2]^T
// 8 warps (2x4), warp tile 64x64, BK=32, 4-stage cp.async, LDSM.x4 loads.
__device__ __forceinline__ void gemm_body(
    const __half* __restrict__ A, const __half* __restrict__ B,
    const float* __restrict__ bias, float* __restrict__ C,
    int Ntot, int m0, int n0, unsigned char* sm)
{
    const int tid = threadIdx.x;
    const int wid = tid >> 5, lane = tid & 31;
    const int wr = wid >> 2, wc = wid & 3;    // warp grid 2x4, warp tile 64x64

    const unsigned char* Ag = (const unsigned char*)A + (size_t)m0 * (K2 * 2);
    const unsigned char* Bg = (const unsigned char*)B + (size_t)n0 * (K2 * 2);

    const uint32_t smb = smem_to_u32(sm);
    const int lr = tid >> 1, lh = tid & 1;            // loader: row, 32B half
    const uint32_t adst = smb + lr * AROWB + lh * 32;
    const uint32_t bdst = adst + ASZ;
    const size_t goff = (size_t)lr * (K2 * 2) + lh * 32;

    // ldmatrix lane bases
    const uint32_t a_lm = smb + (uint32_t)(wr * 64 + (lane & 15)) * AROWB + (lane >> 4) * 16;
    const uint32_t b_lm = smb + ASZ
        + (uint32_t)(wc * 64 + (lane >> 4) * 8 + (lane & 7)) * AROWB
        + ((lane >> 3) & 1) * 16;

    auto load_stage = [&](int st, int c) {
        uint32_t d = st * STAGE;
        const unsigned char* ag = Ag + goff + c * 64;
        cp16(adst + d, ag);
        cp16(adst + d + 16, ag + 16);
        const unsigned char* bg0 = Bg + goff + c * 64;
        const unsigned char* bg1 = bg0 + (size_t)128 * (K2 * 2);
        cp16(bdst + d, bg0);
        cp16(bdst + d + 16, bg0 + 16);
        cp16(bdst + d + 128 * AROWB, bg1);
        cp16(bdst + d + 128 * AROWB + 16, bg1 + 16);
        asm volatile("cp.async.commit_group;" ::: "memory");
    };

    float acc[4][8][4];
#pragma unroll
    for (int i = 0; i < 4; i++)
#pragma unroll
        for (int j = 0; j < 8; j++)
#pragma unroll
            for (int k = 0; k < 4; k++) acc[i][j][k] = 0.f;

#pragma unroll
    for (int s = 0; s < STAGES - 1; s++) load_stage(s, s);

    const int NCHUNK = K2 / 32;   // 64
    for (int c = 0; c < NCHUNK; c++) {
        const int st = c & (STAGES - 1);
        asm volatile("cp.async.wait_group %0;" :: "n"(STAGES - 2) : "memory");
        __syncthreads();
        if (c + STAGES - 1 < NCHUNK) load_stage((c + STAGES - 1) & (STAGES - 1), c + STAGES - 1);

        const uint32_t soff = st * STAGE;
#pragma unroll
        for (int ks = 0; ks < 2; ks++) {
            const uint32_t ko = soff + ks * 32;
            uint32_t a[4][4], b[8][2];
#pragma unroll
            for (int mi = 0; mi < 4; mi++)
                ldsm4(a[mi], a_lm + ko + (uint32_t)(mi * 16) * AROWB);
#pragma unroll
            for (int j = 0; j < 4; j++) {
                uint32_t r4[4];
                ldsm4(r4, b_lm + ko + (uint32_t)(j * 16) * AROWB);
                b[2 * j][0] = r4[0]; b[2 * j][1] = r4[1];
                b[2 * j + 1][0] = r4[2]; b[2 * j + 1][1] = r4[3];
            }
#pragma unroll
            for (int mi = 0; mi < 4; mi++)
#pragma unroll
                for (int ni = 0; ni < 8; ni++)
                    mma16816(acc[mi][ni], a[mi], b[ni]);
        }
    }

    // epilogue: bias + direct STG
    const int ccol = n0 + wc * 64 + (lane & 3) * 2;
    float bvv[8][2];
#pragma unroll
    for (int ni = 0; ni < 8; ni++) {
        bvv[ni][0] = bias[ccol + ni * 8];
        bvv[ni][1] = bias[ccol + ni * 8 + 1];
    }
    const int crow = m0 + wr * 64 + (lane >> 2);
#pragma unroll
    for (int mi = 0; mi < 4; mi++) {
#pragma unroll
        for (int hf = 0; hf < 2; hf++) {
            float* cp = C + (size_t)(crow + mi * 16 + hf * 8) * Ntot + ccol;
#pragma unroll
            for (int ni = 0; ni < 8; ni++) {
                float2 v = make_float2(acc[mi][ni][hf * 2] + bvv[ni][0],
                                       acc[mi][ni][hf * 2 + 1] + bvv[ni][1]);
                *(float2*)(cp + ni * 8) = v;
            }
        }
    }
}

// Merged projection GEMMs: blocks 0..191 -> C1 (2048x3072), 192..575 -> C23
__global__ __launch_bounds__(256) void gemm_merged() {
    extern __shared__ __align__(16) unsigned char sm[];
    int bid = blockIdx.x;
    if (bid < 192) {
        int mb = bid / 12, nb = bid % 12;
        gemm_body(g_afsq, g_bqkv, g_bias3, g_C1, 3072, mb * 128, nb * 256, sm);
    } else {
        int t = bid - 192;
        int mb = t / 8, nb = t % 8;
        gemm_body(g_apx, g_bqkv + (size_t)1024 * K2, g_bias3 + 1024, g_C23,
                  2048, mb * 128, nb * 256, sm);
    }
}

// Output GEMM: out[4096,1024] = aatt @ bo^T + bo_bias
__global__ __launch_bounds__(256) void gemm_out(const float* __restrict__ bias,
                                                float* __restrict__ C) {
    extern __shared__ __align__(16) unsigned char sm[];
    gemm_body(g_aatt, g_bo, bias, C, 1024, blockIdx.y * 128, blockIdx.x * 256, sm);
}

// ---------------- attention (smem scores, single-expf-per-key) --------------
__global__ __launch_bounds__(256) void attn_kernel(const float* __restrict__ bk,
                                                   const float* __restrict__ bv) {
    __shared__ float ssc[8][34];
    const int w = threadIdx.x >> 5;
    const int gw = (blockIdx.x * 256 + threadIdx.x) >> 5;
    const int lane = threadIdx.x & 31;
    const int s = gw & (SS - 1);
    const int h = (gw >> 11) & (HH - 1);
    const int b = gw >> 15;
    const int e = (h << 6) + 2 * lane;   // this thread covers elements e, e+1

    float* mysc = ssc[w];
    const float* xkv = g_C23 + (size_t)2048 * 2048;   // xk|xv rows

    const float2 q = *(const float2*)(g_C1 + (size_t)s * 3072 + e);

#pragma unroll
    for (int k = 0; k < WW; k++) {
        const int t = s + k - 15;
        float2 kv;
        if ((unsigned)t < SS) kv = *(const float2*)(xkv + (size_t)((b << 11) + t) * 2048 + e);
        else                  kv = *(const float2*)(bk + e);
        float p = q.x * kv.x + q.y * kv.y;
#pragma unroll
        for (int o = 16; o; o >>= 1) p += __shfl_xor_sync(0xffffffffu, p, o);
        if (lane == 0) mysc[k] = p * 0.125f;
    }
    {
        const float2 kv = *(const float2*)(g_C23 + (size_t)s * 2048 + e);
        float p = q.x * kv.x + q.y * kv.y;
#pragma unroll
        for (int o = 16; o; o >>= 1) p += __shfl_xor_sync(0xffffffffu, p, o);
        if (lane == 0) mysc[31] = p * 0.125f;
    }
    {
        const float2 kv = *(const float2*)(g_C1 + (size_t)s * 3072 + 1024 + e);
        float p = q.x * kv.x + q.y * kv.y;
#pragma unroll
        for (int o = 16; o; o >>= 1) p += __shfl_xor_sync(0xffffffffu, p, o);
        if (lane == 0) mysc[32] = p * 0.125f;
    }
    __syncwarp();

    float m = mysc[0];
#pragma unroll
    for (int k = 1; k < 33; k++) m = fmaxf(m, mysc[k]);

    float svk = mysc[lane];
    float ex = expf(svk - m);
    float ex32 = (lane == 0) ? expf(mysc[32] - m) : 0.f;
    __syncwarp();
    mysc[lane] = ex;
    if (lane == 0) mysc[32] = ex32;
    __syncwarp();

    float denom = 0.f;
#pragma unroll
    for (int k = 0; k < 33; k++) denom += mysc[k];
    const float inv = 1.f / denom;

    float o0 = 0.f, o1 = 0.f;
#pragma unroll
    for (int k = 0; k < WW; k++) {
        const int t = s + k - 15;
        float2 vv;
        if ((unsigned)t < SS) vv = *(const float2*)(xkv + (size_t)((b << 11) + t) * 2048 + 1024 + e);
        else                  vv = *(const float2*)(bv + e);
        const float wk = mysc[k];
        o0 += wk * vv.x; o1 += wk * vv.y;
    }
    {
        const float2 vv = *(const float2*)(g_C23 + (size_t)s * 2048 + 1024 + e);
        o0 += mysc[31] * vv.x; o1 += mysc[31] * vv.y;
    }
    {
        const float2 vv = *(const float2*)(g_C1 + (size_t)s * 3072 + 2048 + e);
        o0 += mysc[32] * vv.x; o1 += mysc[32] * vv.y;
    }

    // write fp16 (h,l) pairs for elements e, e+1 straight into g_aatt
    unsigned short h0, l0, h1, l1;
    split2f(o0 * inv, h0, l0);
    split2f(o1 * inv, h1, l1);
    const int row = (b << 11) + s;
    uint2* p64 = (uint2*)(g_aatt + (size_t)row * K2 + 2 * e);
    *p64 = make_uint2((uint32_t)h0 | ((uint32_t)l0 << 16),
                      (uint32_t)h1 | ((uint32_t)l1 << 16));
}

// ---------------- launch ----------------------------------------------------
extern "C" void kernel_launch(void* const* d_in, const int* in_sizes, int n_in,
                              void* d_out, int out_size) {
    const float* x   = (const float*)d_in[0];
    const float* fsq = (const float*)d_in[1];
    const float* pos = (const float*)d_in[2];
    const float* Wq  = (const float*)d_in[3];
    const float* bq  = (const float*)d_in[4];
    const float* Wk  = (const float*)d_in[5];
    const float* bk  = (const float*)d_in[6];
    const float* Wv  = (const float*)d_in[7];
    const float* bv  = (const float*)d_in[8];
    const float* Wo  = (const float*)d_in[9];
    const float* bo  = (const float*)d_in[10];
    float* out = (float*)d_out;

    cudaFuncSetAttribute(gemm_merged, cudaFuncAttributeMaxDynamicSharedMemorySize, SMEMSZ);
    cudaFuncSetAttribute(gemm_out,    cudaFuncAttributeMaxDynamicSharedMemorySize, SMEMSZ);

    prep_all<<<6144, 256>>>(x, fsq, pos, Wq, Wk, Wv, Wo, bq, bk, bv);
    gemm_merged<<<576, 256, SMEMSZ>>>();
    attn_kernel<<<8192, 256>>>(bk, bv);
    gemm_out<<<dim3(4, 32), 256, SMEMSZ>>>(bo, out);
}

// round 12
// speedup vs baseline: 1.5693x; 1.1096x over previous
#include <cuda_runtime.h>
#include <cuda_bf16.h>
#include <cuda_fp16.h>
#include <cstdint>

#define BB 2
#define SS 2048
#define HH 16
#define WW 31
#define K2 2048            // fp16 interleave-2: 1024 fp32 -> 2048 fp16
#define STAGES 4
#define AROWB 80           // padded smem row bytes (32 fp16 + 8 pad)
#define ASZ (128 * AROWB)  // A stage bytes
#define BSZ (256 * AROWB)  // B stage bytes
#define STAGE (ASZ + BSZ)  // 30720
#define SMEMSZ (STAGES * STAGE)

// ---------------- device scratch -------------------------------------------
__device__ __align__(16) __half g_afsq[2048u * K2];
__device__ __align__(16) __half g_apx [6144u * K2];   // [pos(2048); x(4096)]
__device__ __align__(16) __half g_aatt[4096u * K2];
__device__ __align__(16) __half g_bqkv[3072u * K2];
__device__ __align__(16) __half g_bo  [1024u * K2];
__device__ float g_C1 [2048u * 3072];   // [qh | fsqk | fsqv]
__device__ float g_C23[6144u * 2048];   // rows 0-2047: [posk|posv]; 2048+: [xk|xv]
__device__ float g_bias3[3072];

// ---------------- helpers ---------------------------------------------------
__device__ __forceinline__ uint32_t smem_to_u32(const void* p) {
    uint32_t a;
    asm("{ .reg .u64 t; cvta.to.shared.u64 t, %1; cvt.u32.u64 %0, t; }"
        : "=r"(a) : "l"(p));
    return a;
}
__device__ __forceinline__ void cp16(uint32_t s, const void* g) {
    asm volatile("cp.async.cg.shared.global [%0], [%1], 16;" :: "r"(s), "l"(g));
}
__device__ __forceinline__ void ldsm4(uint32_t* r, uint32_t addr) {
    asm volatile("ldmatrix.sync.aligned.m8n8.x4.shared.b16 {%0,%1,%2,%3}, [%4];"
                 : "=r"(r[0]), "=r"(r[1]), "=r"(r[2]), "=r"(r[3]) : "r"(addr));
}
__device__ __forceinline__ void mma16816(float* c, const uint32_t* a, const uint32_t* b) {
    asm volatile(
        "mma.sync.aligned.m16n8k16.row.col.f32.f16.f16.f32 "
        "{%0,%1,%2,%3}, {%4,%5,%6,%7}, {%8,%9}, {%0,%1,%2,%3};"
        : "+f"(c[0]), "+f"(c[1]), "+f"(c[2]), "+f"(c[3])
        : "r"(a[0]), "r"(a[1]), "r"(a[2]), "r"(a[3]), "r"(b[0]), "r"(b[1]));
}
// fp16 split: h = fp16(a), l = fp16(a - h)
__device__ __forceinline__ void split2f(float a, unsigned short& h, unsigned short& l) {
    __half hb = __float2half_rn(a);
    __half lb = __float2half_rn(a - __half2float(hb));
    h = __half_as_ushort(hb);
    l = __half_as_ushort(lb);
}

// pack 8 fp32 -> 16 fp16 pairs -> 2x uint4 stores.
// a_side: (h, l);  b_side: (h, h)
template <bool ASIDE>
__device__ __forceinline__ void pack_pairs(const float* f, __half* dst) {
    uint32_t u[8];
#pragma unroll
    for (int i = 0; i < 8; i++) {
        unsigned short h, l;
        split2f(f[i], h, l);
        u[i] = (uint32_t)h | ((uint32_t)(ASIDE ? l : h) << 16);
    }
    uint4* q = (uint4*)dst;
    q[0] = make_uint4(u[0], u[1], u[2], u[3]);
    q[1] = make_uint4(u[4], u[5], u[6], u[7]);
}

// ---------------- merged prep kernel ----------------------------------------
// blocks 0..2047: weights+bias. Coalesced mapping: adjacent threads handle
// adjacent output columns n (adjacent e within a head) at fixed k-block kb.
// blocks 2048..6143: activations (fsq -> afsq; pos,x -> apx).
__global__ __launch_bounds__(256) void prep_all(
    const float* __restrict__ x, const float* __restrict__ fsq,
    const float* __restrict__ pos,
    const float* __restrict__ Wq, const float* __restrict__ Wk,
    const float* __restrict__ Wv, const float* __restrict__ Wo,
    const float* __restrict__ bq, const float* __restrict__ bk,
    const float* __restrict__ bv) {
    if (blockIdx.x < 2048) {
        int gi = blockIdx.x * 256 + threadIdx.x;   // 128 * 4096
        int kb = gi >> 12;          // 0..127
        int n  = gi & 4095;         // 0..4095
        if (kb == 0 && n < 3072)
            g_bias3[n] = n < 1024 ? bq[n] : (n < 2048 ? bk[n - 1024] : bv[n - 2048]);
        float f[8];
        if (n < 3072) {
            int sel = n >> 10, nn = n & 1023, h = nn >> 6, e = nn & 63;
            const float* W = sel == 0 ? Wq : (sel == 1 ? Wk : Wv);
            const float* src = W + ((size_t)h << 16) + (size_t)(kb * 8) * 64 + e;
#pragma unroll
            for (int i = 0; i < 8; i++) f[i] = src[i * 64];
            pack_pairs<false>(f, g_bqkv + (size_t)n * K2 + kb * 16);
        } else {
            int n2 = n - 3072;
#pragma unroll
            for (int i = 0; i < 8; i++) f[i] = Wo[(size_t)(kb * 8 + i) * 1024 + n2];
            pack_pairs<false>(f, g_bo + (size_t)n2 * K2 + kb * 16);
        }
    } else {
        int idx = (blockIdx.x - 2048) * 256 + threadIdx.x;   // 8192*128
        int r = idx >> 7, k8 = idx & 127;
        const float* src;
        __half* dst;
        if (r < 2048)      { src = fsq + (size_t)r * 1024;          dst = g_afsq + (size_t)r * K2; }
        else if (r < 4096) { src = pos + (size_t)(r - 2048) * 1024; dst = g_apx + (size_t)(r - 2048) * K2; }
        else               { src = x   + (size_t)(r - 4096) * 1024; dst = g_apx + (size_t)(r - 2048) * K2; }
        const float4* p = (const float4*)(src + k8 * 8);
        float4 v0 = p[0], v1 = p[1];
        float f[8] = {v0.x, v0.y, v0.z, v0.w, v1.x, v1.y, v1.z, v1.w};
        pack_pairs<true>(f, dst + k8 * 16);
    }
}

// ---------------- fp16 mma.sync GEMM body (ldmatrix feed) --------------------
__device__ __forceinline__ void gemm_body(
    const __half* __restrict__ A, const __half* __restrict__ B,
    const float* __restrict__ bias, float* __restrict__ C,
    int Ntot, int m0, int n0, unsigned char* sm)
{
    const int tid = threadIdx.x;
    const int wid = tid >> 5, lane = tid & 31;
    const int wr = wid >> 2, wc = wid & 3;    // warp grid 2x4, warp tile 64x64

    const unsigned char* Ag = (const unsigned char*)A + (size_t)m0 * (K2 * 2);
    const unsigned char* Bg = (const unsigned char*)B + (size_t)n0 * (K2 * 2);

    const uint32_t smb = smem_to_u32(sm);
    const int lr = tid >> 1, lh = tid & 1;            // loader: row, 32B half
    const uint32_t adst = smb + lr * AROWB + lh * 32;
    const uint32_t bdst = adst + ASZ;
    const size_t goff = (size_t)lr * (K2 * 2) + lh * 32;

    const uint32_t a_lm = smb + (uint32_t)(wr * 64 + (lane & 15)) * AROWB + (lane >> 4) * 16;
    const uint32_t b_lm = smb + ASZ
        + (uint32_t)(wc * 64 + (lane >> 4) * 8 + (lane & 7)) * AROWB
        + ((lane >> 3) & 1) * 16;

    auto load_stage = [&](int st, int c) {
        uint32_t d = st * STAGE;
        const unsigned char* ag = Ag + goff + c * 64;
        cp16(adst + d, ag);
        cp16(adst + d + 16, ag + 16);
        const unsigned char* bg0 = Bg + goff + c * 64;
        const unsigned char* bg1 = bg0 + (size_t)128 * (K2 * 2);
        cp16(bdst + d, bg0);
        cp16(bdst + d + 16, bg0 + 16);
        cp16(bdst + d + 128 * AROWB, bg1);
        cp16(bdst + d + 128 * AROWB + 16, bg1 + 16);
        asm volatile("cp.async.commit_group;" ::: "memory");
    };

    float acc[4][8][4];
#pragma unroll
    for (int i = 0; i < 4; i++)
#pragma unroll
        for (int j = 0; j < 8; j++)
#pragma unroll
            for (int k = 0; k < 4; k++) acc[i][j][k] = 0.f;

#pragma unroll
    for (int s = 0; s < STAGES - 1; s++) load_stage(s, s);

    const int NCHUNK = K2 / 32;   // 64
    for (int c = 0; c < NCHUNK; c++) {
        const int st = c & (STAGES - 1);
        asm volatile("cp.async.wait_group %0;" :: "n"(STAGES - 2) : "memory");
        __syncthreads();
        if (c + STAGES - 1 < NCHUNK) load_stage((c + STAGES - 1) & (STAGES - 1), c + STAGES - 1);

        const uint32_t soff = st * STAGE;
#pragma unroll
        for (int ks = 0; ks < 2; ks++) {
            const uint32_t ko = soff + ks * 32;
            uint32_t a[4][4], b[8][2];
#pragma unroll
            for (int mi = 0; mi < 4; mi++)
                ldsm4(a[mi], a_lm + ko + (uint32_t)(mi * 16) * AROWB);
#pragma unroll
            for (int j = 0; j < 4; j++) {
                uint32_t r4[4];
                ldsm4(r4, b_lm + ko + (uint32_t)(j * 16) * AROWB);
                b[2 * j][0] = r4[0]; b[2 * j][1] = r4[1];
                b[2 * j + 1][0] = r4[2]; b[2 * j + 1][1] = r4[3];
            }
#pragma unroll
            for (int mi = 0; mi < 4; mi++)
#pragma unroll
                for (int ni = 0; ni < 8; ni++)
                    mma16816(acc[mi][ni], a[mi], b[ni]);
        }
    }

    const int ccol = n0 + wc * 64 + (lane & 3) * 2;
    float bvv[8][2];
#pragma unroll
    for (int ni = 0; ni < 8; ni++) {
        bvv[ni][0] = bias[ccol + ni * 8];
        bvv[ni][1] = bias[ccol + ni * 8 + 1];
    }
    const int crow = m0 + wr * 64 + (lane >> 2);
#pragma unroll
    for (int mi = 0; mi < 4; mi++) {
#pragma unroll
        for (int hf = 0; hf < 2; hf++) {
            float* cp = C + (size_t)(crow + mi * 16 + hf * 8) * Ntot + ccol;
#pragma unroll
            for (int ni = 0; ni < 8; ni++) {
                float2 v = make_float2(acc[mi][ni][hf * 2] + bvv[ni][0],
                                       acc[mi][ni][hf * 2 + 1] + bvv[ni][1]);
                *(float2*)(cp + ni * 8) = v;
            }
        }
    }
}

// Merged projection GEMMs: blocks 0..191 -> C1 (2048x3072), 192..575 -> C23
__global__ __launch_bounds__(256) void gemm_merged() {
    extern __shared__ __align__(16) unsigned char sm[];
    int bid = blockIdx.x;
    if (bid < 192) {
        int mb = bid / 12, nb = bid % 12;
        gemm_body(g_afsq, g_bqkv, g_bias3, g_C1, 3072, mb * 128, nb * 256, sm);
    } else {
        int t = bid - 192;
        int mb = t / 8, nb = t % 8;
        gemm_body(g_apx, g_bqkv + (size_t)1024 * K2, g_bias3 + 1024, g_C23,
                  2048, mb * 128, nb * 256, sm);
    }
}

// Output GEMM: out[4096,1024] = aatt @ bo^T + bo_bias
__global__ __launch_bounds__(256) void gemm_out(const float* __restrict__ bias,
                                                float* __restrict__ C) {
    extern __shared__ __align__(16) unsigned char sm[];
    gemm_body(g_aatt, g_bo, bias, C, 1024, blockIdx.y * 128, blockIdx.x * 256, sm);
}

// ---------------- attention: smem-tiled window ------------------------------
// Block = 8 consecutive s for one (b,h). The 8 warps share a 38-row K/V
// window staged in smem (7x traffic reduction vs per-warp streaming).
__global__ __launch_bounds__(256) void attn_kernel(const float* __restrict__ bk,
                                                   const float* __restrict__ bv) {
    __shared__ float sk[38][64];
    __shared__ float sv[38][64];
    __shared__ float ssc[8][34];

    const int bid = blockIdx.x;
    const int s0 = (bid & 255) << 3;        // 256 s-tiles of 8
    const int h  = (bid >> 8) & 15;
    const int b  = bid >> 12;
    const int tid = threadIdx.x;

    const float* xkv = g_C23 + (size_t)2048 * 2048;   // xk|xv rows

    // stage K/V window rows t = s0-15 .. s0+22
    for (int i = tid; i < 38 * 16; i += 256) {
        const int r = i >> 4, j4 = (i & 15) << 2;
        const int t = s0 - 15 + r;
        float4 k4, v4;
        if ((unsigned)t < SS) {
            const float* base = xkv + (size_t)((b << 11) + t) * 2048 + (h << 6);
            k4 = *(const float4*)(base + j4);
            v4 = *(const float4*)(base + 1024 + j4);
        } else {
            k4 = *(const float4*)(bk + (h << 6) + j4);
            v4 = *(const float4*)(bv + (h << 6) + j4);
        }
        *(float4*)(&sk[r][j4]) = k4;
        *(float4*)(&sv[r][j4]) = v4;
    }
    __syncthreads();

    const int w = tid >> 5, lane = tid & 31;
    const int s = s0 + w;
    const int e = (h << 6) + 2 * lane;
    float* mysc = ssc[w];

    const float2 q = *(const float2*)(g_C1 + (size_t)s * 3072 + e);

    // ---- scores ----
#pragma unroll
    for (int k = 0; k < WW; k++) {
        const float2 kv = *(const float2*)(&sk[w + k][2 * lane]);
        float p = q.x * kv.x + q.y * kv.y;
#pragma unroll
        for (int o = 16; o; o >>= 1) p += __shfl_xor_sync(0xffffffffu, p, o);
        if (lane == 0) mysc[k] = p * 0.125f;
    }
    {
        const float2 kv = *(const float2*)(g_C23 + (size_t)s * 2048 + e);
        float p = q.x * kv.x + q.y * kv.y;
#pragma unroll
        for (int o = 16; o; o >>= 1) p += __shfl_xor_sync(0xffffffffu, p, o);
        if (lane == 0) mysc[31] = p * 0.125f;
    }
    {
        const float2 kv = *(const float2*)(g_C1 + (size_t)s * 3072 + 1024 + e);
        float p = q.x * kv.x + q.y * kv.y;
#pragma unroll
        for (int o = 16; o; o >>= 1) p += __shfl_xor_sync(0xffffffffu, p, o);
        if (lane == 0) mysc[32] = p * 0.125f;
    }
    __syncwarp();

    float m = mysc[0];
#pragma unroll
    for (int k = 1; k < 33; k++) m = fmaxf(m, mysc[k]);

    float svk = mysc[lane];
    float ex = expf(svk - m);
    float ex32 = (lane == 0) ? expf(mysc[32] - m) : 0.f;
    __syncwarp();
    mysc[lane] = ex;
    if (lane == 0) mysc[32] = ex32;
    __syncwarp();

    float denom = 0.f;
#pragma unroll
    for (int k = 0; k < 33; k++) denom += mysc[k];
    const float inv = 1.f / denom;

    // ---- V aggregation ----
    float o0 = 0.f, o1 = 0.f;
#pragma unroll
    for (int k = 0; k < WW; k++) {
        const float2 vv = *(const float2*)(&sv[w + k][2 * lane]);
        const float wk = mysc[k];
        o0 += wk * vv.x; o1 += wk * vv.y;
    }
    {
        const float2 vv = *(const float2*)(g_C23 + (size_t)s * 2048 + 1024 + e);
        o0 += mysc[31] * vv.x; o1 += mysc[31] * vv.y;
    }
    {
        const float2 vv = *(const float2*)(g_C1 + (size_t)s * 3072 + 2048 + e);
        o0 += mysc[32] * vv.x; o1 += mysc[32] * vv.y;
    }

    // write fp16 (h,l) pairs for elements e, e+1 straight into g_aatt
    unsigned short h0, l0, h1, l1;
    split2f(o0 * inv, h0, l0);
    split2f(o1 * inv, h1, l1);
    const int row = (b << 11) + s;
    uint2* p64 = (uint2*)(g_aatt + (size_t)row * K2 + 2 * e);
    *p64 = make_uint2((uint32_t)h0 | ((uint32_t)l0 << 16),
                      (uint32_t)h1 | ((uint32_t)l1 << 16));
}

// ---------------- launch ----------------------------------------------------
extern "C" void kernel_launch(void* const* d_in, const int* in_sizes, int n_in,
                              void* d_out, int out_size) {
    const float* x   = (const float*)d_in[0];
    const float* fsq = (const float*)d_in[1];
    const float* pos = (const float*)d_in[2];
    const float* Wq  = (const float*)d_in[3];
    const float* bq  = (const float*)d_in[4];
    const float* Wk  = (const float*)d_in[5];
    const float* bk  = (const float*)d_in[6];
    const float* Wv  = (const float*)d_in[7];
    const float* bv  = (const float*)d_in[8];
    const float* Wo  = (const float*)d_in[9];
    const float* bo  = (const float*)d_in[10];
    float* out = (float*)d_out;

    cudaFuncSetAttribute(gemm_merged, cudaFuncAttributeMaxDynamicSharedMemorySize, SMEMSZ);
    cudaFuncSetAttribute(gemm_out,    cudaFuncAttributeMaxDynamicSharedMemorySize, SMEMSZ);

    prep_all<<<6144, 256>>>(x, fsq, pos, Wq, Wk, Wv, Wo, bq, bk, bv);
    gemm_merged<<<576, 256, SMEMSZ>>>();
    attn_kernel<<<8192, 256>>>(bk, bv);
    gemm_out<<<dim3(4, 32), 256, SMEMSZ>>>(bo, out);
}

// round 13
// speedup vs baseline: 1.5965x; 1.0173x over previous
#include <cuda_runtime.h>
#include <cuda_bf16.h>
#include <cuda_fp16.h>
#include <cstdint>

#define BB 2
#define SS 2048
#define HH 16
#define WW 31
#define K2 2048            // fp16 interleave-2: 1024 fp32 -> 2048 fp16
#define STAGES 4
#define AROWB 80           // padded smem row bytes (32 fp16 + 8 pad)
#define ASZ (128 * AROWB)  // A stage bytes
#define BSZ (256 * AROWB)  // B stage bytes
#define STAGE (ASZ + BSZ)  // 30720
#define SMEMSZ (STAGES * STAGE)

// ---------------- device scratch -------------------------------------------
__device__ __align__(16) __half g_afsq[2048u * K2];
__device__ __align__(16) __half g_apx [6144u * K2];   // [pos(2048); x(4096)]
__device__ __align__(16) __half g_aatt[4096u * K2];
__device__ __align__(16) __half g_bqkv[3072u * K2];
__device__ __align__(16) __half g_bo  [1024u * K2];
__device__ float g_C1 [2048u * 3072];   // [qh | fsqk | fsqv]
__device__ float g_C23[6144u * 2048];   // rows 0-2047: [posk|posv]; 2048+: [xk|xv]
__device__ float g_bias3[3072];

// ---------------- helpers ---------------------------------------------------
__device__ __forceinline__ uint32_t smem_to_u32(const void* p) {
    uint32_t a;
    asm("{ .reg .u64 t; cvta.to.shared.u64 t, %1; cvt.u32.u64 %0, t; }"
        : "=r"(a) : "l"(p));
    return a;
}
__device__ __forceinline__ void cp16(uint32_t s, const void* g) {
    asm volatile("cp.async.cg.shared.global [%0], [%1], 16;" :: "r"(s), "l"(g));
}
__device__ __forceinline__ void ldsm4(uint32_t* r, uint32_t addr) {
    asm volatile("ldmatrix.sync.aligned.m8n8.x4.shared.b16 {%0,%1,%2,%3}, [%4];"
                 : "=r"(r[0]), "=r"(r[1]), "=r"(r[2]), "=r"(r[3]) : "r"(addr));
}
__device__ __forceinline__ void mma16816(float* c, const uint32_t* a, const uint32_t* b) {
    asm volatile(
        "mma.sync.aligned.m16n8k16.row.col.f32.f16.f16.f32 "
        "{%0,%1,%2,%3}, {%4,%5,%6,%7}, {%8,%9}, {%0,%1,%2,%3};"
        : "+f"(c[0]), "+f"(c[1]), "+f"(c[2]), "+f"(c[3])
        : "r"(a[0]), "r"(a[1]), "r"(a[2]), "r"(a[3]), "r"(b[0]), "r"(b[1]));
}
// fp16 split: h = fp16(a), l = fp16(a - h)
__device__ __forceinline__ void split2f(float a, unsigned short& h, unsigned short& l) {
    __half hb = __float2half_rn(a);
    __half lb = __float2half_rn(a - __half2float(hb));
    h = __half_as_ushort(hb);
    l = __half_as_ushort(lb);
}

// pack 8 fp32 -> 16 fp16 pairs -> 2x uint4 stores.
// a_side: (h, l);  b_side: (h, h)
template <bool ASIDE>
__device__ __forceinline__ void pack_pairs(const float* f, __half* dst) {
    uint32_t u[8];
#pragma unroll
    for (int i = 0; i < 8; i++) {
        unsigned short h, l;
        split2f(f[i], h, l);
        u[i] = (uint32_t)h | ((uint32_t)(ASIDE ? l : h) << 16);
    }
    uint4* q = (uint4*)dst;
    q[0] = make_uint4(u[0], u[1], u[2], u[3]);
    q[1] = make_uint4(u[4], u[5], u[6], u[7]);
}

// ---------------- merged prep kernel ----------------------------------------
__global__ __launch_bounds__(256) void prep_all(
    const float* __restrict__ x, const float* __restrict__ fsq,
    const float* __restrict__ pos,
    const float* __restrict__ Wq, const float* __restrict__ Wk,
    const float* __restrict__ Wv, const float* __restrict__ Wo,
    const float* __restrict__ bq, const float* __restrict__ bk,
    const float* __restrict__ bv) {
    if (blockIdx.x < 2048) {
        int gi = blockIdx.x * 256 + threadIdx.x;   // 128 * 4096
        int kb = gi >> 12;          // 0..127
        int n  = gi & 4095;         // 0..4095
        if (kb == 0 && n < 3072)
            g_bias3[n] = n < 1024 ? bq[n] : (n < 2048 ? bk[n - 1024] : bv[n - 2048]);
        float f[8];
        if (n < 3072) {
            int sel = n >> 10, nn = n & 1023, h = nn >> 6, e = nn & 63;
            const float* W = sel == 0 ? Wq : (sel == 1 ? Wk : Wv);
            const float* src = W + ((size_t)h << 16) + (size_t)(kb * 8) * 64 + e;
#pragma unroll
            for (int i = 0; i < 8; i++) f[i] = src[i * 64];
            pack_pairs<false>(f, g_bqkv + (size_t)n * K2 + kb * 16);
        } else {
            int n2 = n - 3072;
#pragma unroll
            for (int i = 0; i < 8; i++) f[i] = Wo[(size_t)(kb * 8 + i) * 1024 + n2];
            pack_pairs<false>(f, g_bo + (size_t)n2 * K2 + kb * 16);
        }
    } else {
        int idx = (blockIdx.x - 2048) * 256 + threadIdx.x;   // 8192*128
        int r = idx >> 7, k8 = idx & 127;
        const float* src;
        __half* dst;
        if (r < 2048)      { src = fsq + (size_t)r * 1024;          dst = g_afsq + (size_t)r * K2; }
        else if (r < 4096) { src = pos + (size_t)(r - 2048) * 1024; dst = g_apx + (size_t)(r - 2048) * K2; }
        else               { src = x   + (size_t)(r - 4096) * 1024; dst = g_apx + (size_t)(r - 2048) * K2; }
        const float4* p = (const float4*)(src + k8 * 8);
        float4 v0 = p[0], v1 = p[1];
        float f[8] = {v0.x, v0.y, v0.z, v0.w, v1.x, v1.y, v1.z, v1.w};
        pack_pairs<true>(f, dst + k8 * 16);
    }
}

// ---------------- fp16 mma.sync GEMM body (ldmatrix feed) --------------------
// Two chunks per __syncthreads: stages used as ping-pong pairs; loads for
// chunks c+2,c+3 overlap the MMAs of chunks c,c+1.
__device__ __forceinline__ void gemm_body(
    const __half* __restrict__ A, const __half* __restrict__ B,
    const float* __restrict__ bias, float* __restrict__ C,
    int Ntot, int m0, int n0, unsigned char* sm)
{
    const int tid = threadIdx.x;
    const int wid = tid >> 5, lane = tid & 31;
    const int wr = wid >> 2, wc = wid & 3;    // warp grid 2x4, warp tile 64x64

    const unsigned char* Ag = (const unsigned char*)A + (size_t)m0 * (K2 * 2);
    const unsigned char* Bg = (const unsigned char*)B + (size_t)n0 * (K2 * 2);

    const uint32_t smb = smem_to_u32(sm);
    const int lr = tid >> 1, lh = tid & 1;            // loader: row, 32B half
    const uint32_t adst = smb + lr * AROWB + lh * 32;
    const uint32_t bdst = adst + ASZ;
    const size_t goff = (size_t)lr * (K2 * 2) + lh * 32;

    const uint32_t a_lm = smb + (uint32_t)(wr * 64 + (lane & 15)) * AROWB + (lane >> 4) * 16;
    const uint32_t b_lm = smb + ASZ
        + (uint32_t)(wc * 64 + (lane >> 4) * 8 + (lane & 7)) * AROWB
        + ((lane >> 3) & 1) * 16;

    auto load_stage = [&](int st, int c) {
        uint32_t d = st * STAGE;
        const unsigned char* ag = Ag + goff + c * 64;
        cp16(adst + d, ag);
        cp16(adst + d + 16, ag + 16);
        const unsigned char* bg0 = Bg + goff + c * 64;
        const unsigned char* bg1 = bg0 + (size_t)128 * (K2 * 2);
        cp16(bdst + d, bg0);
        cp16(bdst + d + 16, bg0 + 16);
        cp16(bdst + d + 128 * AROWB, bg1);
        cp16(bdst + d + 128 * AROWB + 16, bg1 + 16);
        asm volatile("cp.async.commit_group;" ::: "memory");
    };

    float acc[4][8][4];
#pragma unroll
    for (int i = 0; i < 4; i++)
#pragma unroll
        for (int j = 0; j < 8; j++)
#pragma unroll
            for (int k = 0; k < 4; k++) acc[i][j][k] = 0.f;

    load_stage(0, 0);
    load_stage(1, 1);

    const int NCHUNK = K2 / 32;   // 64
    for (int c = 0; c < NCHUNK; c += 2) {
        asm volatile("cp.async.wait_group 0;" ::: "memory");
        __syncthreads();
        if (c + 2 < NCHUNK) {
            load_stage((c + 2) & 3, c + 2);
            load_stage((c + 3) & 3, c + 3);
        }
#pragma unroll
        for (int half = 0; half < 2; half++) {
            const uint32_t soff = ((c + half) & 3) * STAGE;
#pragma unroll
            for (int ks = 0; ks < 2; ks++) {
                const uint32_t ko = soff + ks * 32;
                uint32_t a[4][4], b[8][2];
#pragma unroll
                for (int mi = 0; mi < 4; mi++)
                    ldsm4(a[mi], a_lm + ko + (uint32_t)(mi * 16) * AROWB);
#pragma unroll
                for (int j = 0; j < 4; j++) {
                    uint32_t r4[4];
                    ldsm4(r4, b_lm + ko + (uint32_t)(j * 16) * AROWB);
                    b[2 * j][0] = r4[0]; b[2 * j][1] = r4[1];
                    b[2 * j + 1][0] = r4[2]; b[2 * j + 1][1] = r4[3];
                }
#pragma unroll
                for (int mi = 0; mi < 4; mi++)
#pragma unroll
                    for (int ni = 0; ni < 8; ni++)
                        mma16816(acc[mi][ni], a[mi], b[ni]);
            }
        }
    }

    const int ccol = n0 + wc * 64 + (lane & 3) * 2;
    float bvv[8][2];
#pragma unroll
    for (int ni = 0; ni < 8; ni++) {
        bvv[ni][0] = bias[ccol + ni * 8];
        bvv[ni][1] = bias[ccol + ni * 8 + 1];
    }
    const int crow = m0 + wr * 64 + (lane >> 2);
#pragma unroll
    for (int mi = 0; mi < 4; mi++) {
#pragma unroll
        for (int hf = 0; hf < 2; hf++) {
            float* cp = C + (size_t)(crow + mi * 16 + hf * 8) * Ntot + ccol;
#pragma unroll
            for (int ni = 0; ni < 8; ni++) {
                float2 v = make_float2(acc[mi][ni][hf * 2] + bvv[ni][0],
                                       acc[mi][ni][hf * 2 + 1] + bvv[ni][1]);
                *(float2*)(cp + ni * 8) = v;
            }
        }
    }
}

// Merged projection GEMMs: blocks 0..191 -> C1 (2048x3072), 192..575 -> C23
__global__ __launch_bounds__(256) void gemm_merged() {
    extern __shared__ __align__(16) unsigned char sm[];
    int bid = blockIdx.x;
    if (bid < 192) {
        int mb = bid / 12, nb = bid % 12;
        gemm_body(g_afsq, g_bqkv, g_bias3, g_C1, 3072, mb * 128, nb * 256, sm);
    } else {
        int t = bid - 192;
        int mb = t / 8, nb = t % 8;
        gemm_body(g_apx, g_bqkv + (size_t)1024 * K2, g_bias3 + 1024, g_C23,
                  2048, mb * 128, nb * 256, sm);
    }
}

// Output GEMM: out[4096,1024] = aatt @ bo^T + bo_bias
__global__ __launch_bounds__(256) void gemm_out(const float* __restrict__ bias,
                                                float* __restrict__ C) {
    extern __shared__ __align__(16) unsigned char sm[];
    gemm_body(g_aatt, g_bo, bias, C, 1024, blockIdx.y * 128, blockIdx.x * 256, sm);
}

// ---------------- attention: smem-tiled window ------------------------------
__global__ __launch_bounds__(256) void attn_kernel(const float* __restrict__ bk,
                                                   const float* __restrict__ bv) {
    __shared__ float sk[38][64];
    __shared__ float sv[38][64];
    __shared__ float ssc[8][34];

    const int bid = blockIdx.x;
    const int s0 = (bid & 255) << 3;        // 256 s-tiles of 8
    const int h  = (bid >> 8) & 15;
    const int b  = bid >> 12;
    const int tid = threadIdx.x;

    const float* xkv = g_C23 + (size_t)2048 * 2048;   // xk|xv rows

    for (int i = tid; i < 38 * 16; i += 256) {
        const int r = i >> 4, j4 = (i & 15) << 2;
        const int t = s0 - 15 + r;
        float4 k4, v4;
        if ((unsigned)t < SS) {
            const float* base = xkv + (size_t)((b << 11) + t) * 2048 + (h << 6);
            k4 = *(const float4*)(base + j4);
            v4 = *(const float4*)(base + 1024 + j4);
        } else {
            k4 = *(const float4*)(bk + (h << 6) + j4);
            v4 = *(const float4*)(bv + (h << 6) + j4);
        }
        *(float4*)(&sk[r][j4]) = k4;
        *(float4*)(&sv[r][j4]) = v4;
    }
    __syncthreads();

    const int w = tid >> 5, lane = tid & 31;
    const int s = s0 + w;
    const int e = (h << 6) + 2 * lane;
    float* mysc = ssc[w];

    const float2 q = *(const float2*)(g_C1 + (size_t)s * 3072 + e);

#pragma unroll
    for (int k = 0; k < WW; k++) {
        const float2 kv = *(const float2*)(&sk[w + k][2 * lane]);
        float p = q.x * kv.x + q.y * kv.y;
#pragma unroll
        for (int o = 16; o; o >>= 1) p += __shfl_xor_sync(0xffffffffu, p, o);
        if (lane == 0) mysc[k] = p * 0.125f;
    }
    {
        const float2 kv = *(const float2*)(g_C23 + (size_t)s * 2048 + e);
        float p = q.x * kv.x + q.y * kv.y;
#pragma unroll
        for (int o = 16; o; o >>= 1) p += __shfl_xor_sync(0xffffffffu, p, o);
        if (lane == 0) mysc[31] = p * 0.125f;
    }
    {
        const float2 kv = *(const float2*)(g_C1 + (size_t)s * 3072 + 1024 + e);
        float p = q.x * kv.x + q.y * kv.y;
#pragma unroll
        for (int o = 16; o; o >>= 1) p += __shfl_xor_sync(0xffffffffu, p, o);
        if (lane == 0) mysc[32] = p * 0.125f;
    }
    __syncwarp();

    float m = mysc[0];
#pragma unroll
    for (int k = 1; k < 33; k++) m = fmaxf(m, mysc[k]);

    float svk = mysc[lane];
    float ex = expf(svk - m);
    float ex32 = (lane == 0) ? expf(mysc[32] - m) : 0.f;
    __syncwarp();
    mysc[lane] = ex;
    if (lane == 0) mysc[32] = ex32;
    __syncwarp();

    float denom = 0.f;
#pragma unroll
    for (int k = 0; k < 33; k++) denom += mysc[k];
    const float inv = 1.f / denom;

    float o0 = 0.f, o1 = 0.f;
#pragma unroll
    for (int k = 0; k < WW; k++) {
        const float2 vv = *(const float2*)(&sv[w + k][2 * lane]);
        const float wk = mysc[k];
        o0 += wk * vv.x; o1 += wk * vv.y;
    }
    {
        const float2 vv = *(const float2*)(g_C23 + (size_t)s * 2048 + 1024 + e);
        o0 += mysc[31] * vv.x; o1 += mysc[31] * vv.y;
    }
    {
        const float2 vv = *(const float2*)(g_C1 + (size_t)s * 3072 + 2048 + e);
        o0 += mysc[32] * vv.x; o1 += mysc[32] * vv.y;
    }

    unsigned short h0, l0, h1, l1;
    split2f(o0 * inv, h0, l0);
    split2f(o1 * inv, h1, l1);
    const int row = (b << 11) + s;
    uint2* p64 = (uint2*)(g_aatt + (size_t)row * K2 + 2 * e);
    *p64 = make_uint2((uint32_t)h0 | ((uint32_t)l0 << 16),
                      (uint32_t)h1 | ((uint32_t)l1 << 16));
}

// ---------------- launch ----------------------------------------------------
extern "C" void kernel_launch(void* const* d_in, const int* in_sizes, int n_in,
                              void* d_out, int out_size) {
    const float* x   = (const float*)d_in[0];
    const float* fsq = (const float*)d_in[1];
    const float* pos = (const float*)d_in[2];
    const float* Wq  = (const float*)d_in[3];
    const float* bq  = (const float*)d_in[4];
    const float* Wk  = (const float*)d_in[5];
    const float* bk  = (const float*)d_in[6];
    const float* Wv  = (const float*)d_in[7];
    const float* bv  = (const float*)d_in[8];
    const float* Wo  = (const float*)d_in[9];
    const float* bo  = (const float*)d_in[10];
    float* out = (float*)d_out;

    cudaFuncSetAttribute(gemm_merged, cudaFuncAttributeMaxDynamicSharedMemorySize, SMEMSZ);
    cudaFuncSetAttribute(gemm_out,    cudaFuncAttributeMaxDynamicSharedMemorySize, SMEMSZ);

    prep_all<<<6144, 256>>>(x, fsq, pos, Wq, Wk, Wv, Wo, bq, bk, bv);
    gemm_merged<<<576, 256, SMEMSZ>>>();
    attn_kernel<<<8192, 256>>>(bk, bv);
    gemm_out<<<dim3(4, 32), 256, SMEMSZ>>>(bo, out);
}

// round 14
// speedup vs baseline: 1.6034x; 1.0043x over previous
#include <cuda_runtime.h>
#include <cuda_bf16.h>
#include <cuda_fp16.h>
#include <cstdint>

#define BB 2
#define SS 2048
#define HH 16
#define WW 31
#define K2 2048            // fp16 interleave-2: 1024 fp32 -> 2048 fp16
#define STAGES 4
#define AROWB 80           // padded smem row bytes (32 fp16 + 8 pad)
#define ASZ (128 * AROWB)  // A stage bytes
#define BSZ (256 * AROWB)  // B stage bytes
#define STAGE (ASZ + BSZ)  // 30720
#define SMEMSZ (STAGES * STAGE)

// ---------------- device scratch -------------------------------------------
__device__ __align__(16) __half g_afsq[2048u * K2];
__device__ __align__(16) __half g_apx [6144u * K2];   // [pos(2048); x(4096)]
__device__ __align__(16) __half g_aatt[4096u * K2];
__device__ __align__(16) __half g_bqkv[3072u * K2];
__device__ __align__(16) __half g_bo  [1024u * K2];
__device__ float g_C1 [2048u * 3072];   // [qh | fsqk | fsqv]
__device__ float g_C23[6144u * 2048];   // rows 0-2047: [posk|posv]; 2048+: [xk|xv]
__device__ float g_bias3[3072];

// ---------------- helpers ---------------------------------------------------
__device__ __forceinline__ uint32_t smem_to_u32(const void* p) {
    uint32_t a;
    asm("{ .reg .u64 t; cvta.to.shared.u64 t, %1; cvt.u32.u64 %0, t; }"
        : "=r"(a) : "l"(p));
    return a;
}
__device__ __forceinline__ void cp16(uint32_t s, const void* g) {
    asm volatile("cp.async.cg.shared.global [%0], [%1], 16;" :: "r"(s), "l"(g));
}
__device__ __forceinline__ void ldsm4(uint32_t* r, uint32_t addr) {
    asm volatile("ldmatrix.sync.aligned.m8n8.x4.shared.b16 {%0,%1,%2,%3}, [%4];"
                 : "=r"(r[0]), "=r"(r[1]), "=r"(r[2]), "=r"(r[3]) : "r"(addr));
}
__device__ __forceinline__ void mma16816(float* c, const uint32_t* a, const uint32_t* b) {
    asm volatile(
        "mma.sync.aligned.m16n8k16.row.col.f32.f16.f16.f32 "
        "{%0,%1,%2,%3}, {%4,%5,%6,%7}, {%8,%9}, {%0,%1,%2,%3};"
        : "+f"(c[0]), "+f"(c[1]), "+f"(c[2]), "+f"(c[3])
        : "r"(a[0]), "r"(a[1]), "r"(a[2]), "r"(a[3]), "r"(b[0]), "r"(b[1]));
}
// fp16 split: h = fp16(a), l = fp16(a - h)
__device__ __forceinline__ void split2f(float a, unsigned short& h, unsigned short& l) {
    __half hb = __float2half_rn(a);
    __half lb = __float2half_rn(a - __half2float(hb));
    h = __half_as_ushort(hb);
    l = __half_as_ushort(lb);
}

// pack 8 fp32 -> 16 fp16 pairs -> 2x uint4 stores.
// a_side: (h, l);  b_side: (h, h)
template <bool ASIDE>
__device__ __forceinline__ void pack_pairs(const float* f, __half* dst) {
    uint32_t u[8];
#pragma unroll
    for (int i = 0; i < 8; i++) {
        unsigned short h, l;
        split2f(f[i], h, l);
        u[i] = (uint32_t)h | ((uint32_t)(ASIDE ? l : h) << 16);
    }
    uint4* q = (uint4*)dst;
    q[0] = make_uint4(u[0], u[1], u[2], u[3]);
    q[1] = make_uint4(u[4], u[5], u[6], u[7]);
}

// ---------------- merged prep kernel ----------------------------------------
__global__ __launch_bounds__(256) void prep_all(
    const float* __restrict__ x, const float* __restrict__ fsq,
    const float* __restrict__ pos,
    const float* __restrict__ Wq, const float* __restrict__ Wk,
    const float* __restrict__ Wv, const float* __restrict__ Wo,
    const float* __restrict__ bq, const float* __restrict__ bk,
    const float* __restrict__ bv) {
    if (blockIdx.x < 2048) {
        int gi = blockIdx.x * 256 + threadIdx.x;   // 128 * 4096
        int kb = gi >> 12;          // 0..127
        int n  = gi & 4095;         // 0..4095
        if (kb == 0 && n < 3072)
            g_bias3[n] = n < 1024 ? bq[n] : (n < 2048 ? bk[n - 1024] : bv[n - 2048]);
        float f[8];
        if (n < 3072) {
            int sel = n >> 10, nn = n & 1023, h = nn >> 6, e = nn & 63;
            const float* W = sel == 0 ? Wq : (sel == 1 ? Wk : Wv);
            const float* src = W + ((size_t)h << 16) + (size_t)(kb * 8) * 64 + e;
#pragma unroll
            for (int i = 0; i < 8; i++) f[i] = src[i * 64];
            pack_pairs<false>(f, g_bqkv + (size_t)n * K2 + kb * 16);
        } else {
            int n2 = n - 3072;
#pragma unroll
            for (int i = 0; i < 8; i++) f[i] = Wo[(size_t)(kb * 8 + i) * 1024 + n2];
            pack_pairs<false>(f, g_bo + (size_t)n2 * K2 + kb * 16);
        }
    } else {
        int idx = (blockIdx.x - 2048) * 256 + threadIdx.x;   // 8192*128
        int r = idx >> 7, k8 = idx & 127;
        const float* src;
        __half* dst;
        if (r < 2048)      { src = fsq + (size_t)r * 1024;          dst = g_afsq + (size_t)r * K2; }
        else if (r < 4096) { src = pos + (size_t)(r - 2048) * 1024; dst = g_apx + (size_t)(r - 2048) * K2; }
        else               { src = x   + (size_t)(r - 4096) * 1024; dst = g_apx + (size_t)(r - 2048) * K2; }
        const float4* p = (const float4*)(src + k8 * 8);
        float4 v0 = p[0], v1 = p[1];
        float f[8] = {v0.x, v0.y, v0.z, v0.w, v1.x, v1.y, v1.z, v1.w};
        pack_pairs<true>(f, dst + k8 * 16);
    }
}

// ---------------- fp16 mma.sync GEMM body (ldmatrix feed) --------------------
// Two chunks per __syncthreads: stages used as ping-pong pairs; loads for
// chunks c+2,c+3 overlap the MMAs of chunks c,c+1.
__device__ __forceinline__ void gemm_body(
    const __half* __restrict__ A, const __half* __restrict__ B,
    const float* __restrict__ bias, float* __restrict__ C,
    int Ntot, int m0, int n0, unsigned char* sm)
{
    const int tid = threadIdx.x;
    const int wid = tid >> 5, lane = tid & 31;
    const int wr = wid >> 2, wc = wid & 3;    // warp grid 2x4, warp tile 64x64

    const unsigned char* Ag = (const unsigned char*)A + (size_t)m0 * (K2 * 2);
    const unsigned char* Bg = (const unsigned char*)B + (size_t)n0 * (K2 * 2);

    const uint32_t smb = smem_to_u32(sm);
    const int lr = tid >> 1, lh = tid & 1;            // loader: row, 32B half
    const uint32_t adst = smb + lr * AROWB + lh * 32;
    const uint32_t bdst = adst + ASZ;
    const size_t goff = (size_t)lr * (K2 * 2) + lh * 32;

    const uint32_t a_lm = smb + (uint32_t)(wr * 64 + (lane & 15)) * AROWB + (lane >> 4) * 16;
    const uint32_t b_lm = smb + ASZ
        + (uint32_t)(wc * 64 + (lane >> 4) * 8 + (lane & 7)) * AROWB
        + ((lane >> 3) & 1) * 16;

    auto load_stage = [&](int st, int c) {
        uint32_t d = st * STAGE;
        const unsigned char* ag = Ag + goff + c * 64;
        cp16(adst + d, ag);
        cp16(adst + d + 16, ag + 16);
        const unsigned char* bg0 = Bg + goff + c * 64;
        const unsigned char* bg1 = bg0 + (size_t)128 * (K2 * 2);
        cp16(bdst + d, bg0);
        cp16(bdst + d + 16, bg0 + 16);
        cp16(bdst + d + 128 * AROWB, bg1);
        cp16(bdst + d + 128 * AROWB + 16, bg1 + 16);
        asm volatile("cp.async.commit_group;" ::: "memory");
    };

    float acc[4][8][4];
#pragma unroll
    for (int i = 0; i < 4; i++)
#pragma unroll
        for (int j = 0; j < 8; j++)
#pragma unroll
            for (int k = 0; k < 4; k++) acc[i][j][k] = 0.f;

    load_stage(0, 0);
    load_stage(1, 1);

    const int NCHUNK = K2 / 32;   // 64
    for (int c = 0; c < NCHUNK; c += 2) {
        asm volatile("cp.async.wait_group 0;" ::: "memory");
        __syncthreads();
        if (c + 2 < NCHUNK) {
            load_stage((c + 2) & 3, c + 2);
            load_stage((c + 3) & 3, c + 3);
        }
#pragma unroll
        for (int half = 0; half < 2; half++) {
            const uint32_t soff = ((c + half) & 3) * STAGE;
#pragma unroll
            for (int ks = 0; ks < 2; ks++) {
                const uint32_t ko = soff + ks * 32;
                uint32_t a[4][4], b[8][2];
#pragma unroll
                for (int mi = 0; mi < 4; mi++)
                    ldsm4(a[mi], a_lm + ko + (uint32_t)(mi * 16) * AROWB);
#pragma unroll
                for (int j = 0; j < 4; j++) {
                    uint32_t r4[4];
                    ldsm4(r4, b_lm + ko + (uint32_t)(j * 16) * AROWB);
                    b[2 * j][0] = r4[0]; b[2 * j][1] = r4[1];
                    b[2 * j + 1][0] = r4[2]; b[2 * j + 1][1] = r4[3];
                }
#pragma unroll
                for (int mi = 0; mi < 4; mi++)
#pragma unroll
                    for (int ni = 0; ni < 8; ni++)
                        mma16816(acc[mi][ni], a[mi], b[ni]);
            }
        }
    }

    const int ccol = n0 + wc * 64 + (lane & 3) * 2;
    float bvv[8][2];
#pragma unroll
    for (int ni = 0; ni < 8; ni++) {
        bvv[ni][0] = bias[ccol + ni * 8];
        bvv[ni][1] = bias[ccol + ni * 8 + 1];
    }
    const int crow = m0 + wr * 64 + (lane >> 2);
#pragma unroll
    for (int mi = 0; mi < 4; mi++) {
#pragma unroll
        for (int hf = 0; hf < 2; hf++) {
            float* cp = C + (size_t)(crow + mi * 16 + hf * 8) * Ntot + ccol;
#pragma unroll
            for (int ni = 0; ni < 8; ni++) {
                float2 v = make_float2(acc[mi][ni][hf * 2] + bvv[ni][0],
                                       acc[mi][ni][hf * 2 + 1] + bvv[ni][1]);
                *(float2*)(cp + ni * 8) = v;
            }
        }
    }
}

// Merged projection GEMMs: blocks 0..191 -> C1 (2048x3072), 192..575 -> C23
__global__ __launch_bounds__(256) void gemm_merged() {
    extern __shared__ __align__(16) unsigned char sm[];
    int bid = blockIdx.x;
    if (bid < 192) {
        int mb = bid / 12, nb = bid % 12;
        gemm_body(g_afsq, g_bqkv, g_bias3, g_C1, 3072, mb * 128, nb * 256, sm);
    } else {
        int t = bid - 192;
        int mb = t / 8, nb = t % 8;
        gemm_body(g_apx, g_bqkv + (size_t)1024 * K2, g_bias3 + 1024, g_C23,
                  2048, mb * 128, nb * 256, sm);
    }
}

// Output GEMM: out[4096,1024] = aatt @ bo^T + bo_bias
__global__ __launch_bounds__(256) void gemm_out(const float* __restrict__ bias,
                                                float* __restrict__ C) {
    extern __shared__ __align__(16) unsigned char sm[];
    gemm_body(g_aatt, g_bo, bias, C, 1024, blockIdx.y * 128, blockIdx.x * 256, sm);
}

// ---------------- attention: smem-tiled window, 16-s tiles ------------------
// Block = 16 consecutive s for one (b,h); 16 warps (512 threads) share a
// 54-row K/V window in smem (3.4 staged rows per s vs 4.75 with 8-s tiles).
__global__ __launch_bounds__(512) void attn_kernel(const float* __restrict__ bk,
                                                   const float* __restrict__ bv) {
    __shared__ float sk[54][64];
    __shared__ float sv[54][64];
    __shared__ float ssc[16][34];

    const int bid = blockIdx.x;
    const int s0 = (bid & 127) << 4;        // 128 s-tiles of 16
    const int h  = (bid >> 7) & 15;
    const int b  = bid >> 11;
    const int tid = threadIdx.x;

    const float* xkv = g_C23 + (size_t)2048 * 2048;   // xk|xv rows

    // stage K/V window rows t = s0-15 .. s0+38
    for (int i = tid; i < 54 * 16; i += 512) {
        const int r = i >> 4, j4 = (i & 15) << 2;
        const int t = s0 - 15 + r;
        float4 k4, v4;
        if ((unsigned)t < SS) {
            const float* base = xkv + (size_t)((b << 11) + t) * 2048 + (h << 6);
            k4 = *(const float4*)(base + j4);
            v4 = *(const float4*)(base + 1024 + j4);
        } else {
            k4 = *(const float4*)(bk + (h << 6) + j4);
            v4 = *(const float4*)(bv + (h << 6) + j4);
        }
        *(float4*)(&sk[r][j4]) = k4;
        *(float4*)(&sv[r][j4]) = v4;
    }
    __syncthreads();

    const int w = tid >> 5, lane = tid & 31;
    const int s = s0 + w;
    const int e = (h << 6) + 2 * lane;
    float* mysc = ssc[w];

    const float2 q = *(const float2*)(g_C1 + (size_t)s * 3072 + e);

    // ---- scores ----
#pragma unroll
    for (int k = 0; k < WW; k++) {
        const float2 kv = *(const float2*)(&sk[w + k][2 * lane]);
        float p = q.x * kv.x + q.y * kv.y;
#pragma unroll
        for (int o = 16; o; o >>= 1) p += __shfl_xor_sync(0xffffffffu, p, o);
        if (lane == 0) mysc[k] = p * 0.125f;
    }
    {
        const float2 kv = *(const float2*)(g_C23 + (size_t)s * 2048 + e);
        float p = q.x * kv.x + q.y * kv.y;
#pragma unroll
        for (int o = 16; o; o >>= 1) p += __shfl_xor_sync(0xffffffffu, p, o);
        if (lane == 0) mysc[31] = p * 0.125f;
    }
    {
        const float2 kv = *(const float2*)(g_C1 + (size_t)s * 3072 + 1024 + e);
        float p = q.x * kv.x + q.y * kv.y;
#pragma unroll
        for (int o = 16; o; o >>= 1) p += __shfl_xor_sync(0xffffffffu, p, o);
        if (lane == 0) mysc[32] = p * 0.125f;
    }
    __syncwarp();

    float m = mysc[0];
#pragma unroll
    for (int k = 1; k < 33; k++) m = fmaxf(m, mysc[k]);

    float svk = mysc[lane];
    float ex = expf(svk - m);
    float ex32 = (lane == 0) ? expf(mysc[32] - m) : 0.f;
    __syncwarp();
    mysc[lane] = ex;
    if (lane == 0) mysc[32] = ex32;
    __syncwarp();

    float denom = 0.f;
#pragma unroll
    for (int k = 0; k < 33; k++) denom += mysc[k];
    const float inv = 1.f / denom;

    // ---- V aggregation ----
    float o0 = 0.f, o1 = 0.f;
#pragma unroll
    for (int k = 0; k < WW; k++) {
        const float2 vv = *(const float2*)(&sv[w + k][2 * lane]);
        const float wk = mysc[k];
        o0 += wk * vv.x; o1 += wk * vv.y;
    }
    {
        const float2 vv = *(const float2*)(g_C23 + (size_t)s * 2048 + 1024 + e);
        o0 += mysc[31] * vv.x; o1 += mysc[31] * vv.y;
    }
    {
        const float2 vv = *(const float2*)(g_C1 + (size_t)s * 3072 + 2048 + e);
        o0 += mysc[32] * vv.x; o1 += mysc[32] * vv.y;
    }

    // write fp16 (h,l) pairs for elements e, e+1 straight into g_aatt
    unsigned short h0, l0, h1, l1;
    split2f(o0 * inv, h0, l0);
    split2f(o1 * inv, h1, l1);
    const int row = (b << 11) + s;
    uint2* p64 = (uint2*)(g_aatt + (size_t)row * K2 + 2 * e);
    *p64 = make_uint2((uint32_t)h0 | ((uint32_t)l0 << 16),
                      (uint32_t)h1 | ((uint32_t)l1 << 16));
}

// ---------------- launch ----------------------------------------------------
extern "C" void kernel_launch(void* const* d_in, const int* in_sizes, int n_in,
                              void* d_out, int out_size) {
    const float* x   = (const float*)d_in[0];
    const float* fsq = (const float*)d_in[1];
    const float* pos = (const float*)d_in[2];
    const float* Wq  = (const float*)d_in[3];
    const float* bq  = (const float*)d_in[4];
    const float* Wk  = (const float*)d_in[5];
    const float* bk  = (const float*)d_in[6];
    const float* Wv  = (const float*)d_in[7];
    const float* bv  = (const float*)d_in[8];
    const float* Wo  = (const float*)d_in[9];
    const float* bo  = (const float*)d_in[10];
    float* out = (float*)d_out;

    cudaFuncSetAttribute(gemm_merged, cudaFuncAttributeMaxDynamicSharedMemorySize, SMEMSZ);
    cudaFuncSetAttribute(gemm_out,    cudaFuncAttributeMaxDynamicSharedMemorySize, SMEMSZ);

    prep_all<<<6144, 256>>>(x, fsq, pos, Wq, Wk, Wv, Wo, bq, bk, bv);
    gemm_merged<<<576, 256, SMEMSZ>>>();
    attn_kernel<<<4096, 512>>>(bk, bv);
    gemm_out<<<dim3(4, 32), 256, SMEMSZ>>>(bo, out);
}